// round 3
// baseline (speedup 1.0000x reference)
#include <cuda_runtime.h>
#include <cuda_fp16.h>
#include <math.h>
#include <stdint.h>

#define NTOK 16384
#define DM   2048
#define NE   64
#define CAP  640
#define NCH  128           // k-steps of 16

// ---------------- device scratch ----------------
__device__ int   g_e12[NTOK];
__device__ float g_w12[2 * NTOK];
__device__ int   g_cnt1[NE];
__device__ float g_counts[NE];
__device__ float g_zsum;
// W limbs in B-fragment-friendly permuted layout: [kstep][expert][pair j]
// uint2 per (kstep,expert,j): .x = halves(k=2j,2j+1), .y = halves(k=2j+8,2j+9)
__device__ uint2 g_whp[NCH * NE * 4];   // 256 KB
__device__ uint2 g_wlp[NCH * NE * 4];   // 256 KB

__device__ __forceinline__ uint32_t h2u(__half2 h) { return *reinterpret_cast<uint32_t*>(&h); }

// split float2 -> (hi half2, lo half2 scaled by 2048)
__device__ __forceinline__ void split2(float2 v, uint32_t& hi, uint32_t& lo) {
    __half2 h = __floats2half2_rn(v.x, v.y);
    float2 f = __half22float2(h);
    __half2 l = __floats2half2_rn((v.x - f.x) * 2048.0f, (v.y - f.y) * 2048.0f);
    hi = h2u(h); lo = h2u(l);
}

__device__ __forceinline__ void mma_fp16(float* c,
    uint32_t a0, uint32_t a1, uint32_t a2, uint32_t a3, uint32_t b0, uint32_t b1) {
    asm volatile("mma.sync.aligned.m16n8k16.row.col.f32.f16.f16.f32 "
        "{%0,%1,%2,%3}, {%4,%5,%6,%7}, {%8,%9}, {%0,%1,%2,%3};"
        : "+f"(c[0]), "+f"(c[1]), "+f"(c[2]), "+f"(c[3])
        : "r"(a0), "r"(a1), "r"(a2), "r"(a3), "r"(b0), "r"(b1));
}

// ---------------- W preconvert: fp32 -> two f16 limbs, fragment layout ----------------
__global__ __launch_bounds__(256) void wconv_kernel(const float* __restrict__ W) {
    const int idx = blockIdx.x * 256 + threadIdx.x;   // 32768 total
    const int j = idx & 3, e = (idx >> 2) & 63, c = idx >> 8;
    const float* p = W + (size_t)e * DM + c * 16 + 2 * j;
    float2 v0 = *reinterpret_cast<const float2*>(p);
    float2 v1 = *reinterpret_cast<const float2*>(p + 8);
    uint32_t h0, l0, h1, l1;
    split2(v0, h0, l0);
    split2(v1, h1, l1);
    const int o = (c * 64 + e) * 4 + j;
    g_whp[o] = make_uint2(h0, h1);
    g_wlp[o] = make_uint2(l0, l1);
}

// ---------------- init ----------------
__global__ void init_kernel() {
    int t = threadIdx.x;
    if (t < NE) { g_cnt1[t] = 0; g_counts[t] = 0.0f; }
    if (t == 0) g_zsum = 0.0f;
}

// ---------------- top-2 merge helper (ties -> lower index) ----------------
__device__ __forceinline__ void top2_merge(float& v1, int& i1, float& v2, int& i2, int off) {
    float o1 = __shfl_xor_sync(0xffffffffu, v1, off);
    int  oi1 = __shfl_xor_sync(0xffffffffu, i1, off);
    float o2 = __shfl_xor_sync(0xffffffffu, v2, off);
    int  oi2 = __shfl_xor_sync(0xffffffffu, i2, off);
    bool awins = (v1 > o1) || (v1 == o1 && i1 < oi1);
    if (awins) {
        bool keep = (v2 > o1) || (v2 == o1 && i2 < oi1);
        if (!keep) { v2 = o1; i2 = oi1; }
    } else {
        bool btwo = (o2 > v1) || (o2 == v1 && oi2 < i1);
        float nv2; int ni2;
        if (btwo) { nv2 = o2; ni2 = oi2; }
        else      { nv2 = v1; ni2 = i1; }
        v1 = o1; i1 = oi1; v2 = nv2; i2 = ni2;
    }
}

// ---------------- stage A: HMMA two-limb GEMM + fused epilogue ----------------
__global__ __launch_bounds__(256) void gemm_router(
    const float* __restrict__ x, float* __restrict__ out_rw)
{
    const int tid = threadIdx.x;
    const int w = tid >> 5, lane = tid & 31;
    const int g = lane >> 2, t = lane & 3;
    const int tok0 = blockIdx.x * 128 + w * 16 + g;

    const float* xr0 = x + (size_t)tok0 * DM;
    const float* xr1 = xr0 + (size_t)8 * DM;

    float acc0[8][4], acc1[8][4];
#pragma unroll
    for (int nt = 0; nt < 8; nt++)
#pragma unroll
        for (int q = 0; q < 4; q++) { acc0[nt][q] = 0.0f; acc1[nt][q] = 0.0f; }

    float2 pa[2][4];
#pragma unroll
    for (int b = 0; b < 2; b++) {
        const float* p0 = xr0 + b * 16;
        const float* p1 = xr1 + b * 16;
        pa[b][0] = *reinterpret_cast<const float2*>(p0 + 2 * t);
        pa[b][1] = *reinterpret_cast<const float2*>(p0 + 2 * t + 8);
        pa[b][2] = *reinterpret_cast<const float2*>(p1 + 2 * t);
        pa[b][3] = *reinterpret_cast<const float2*>(p1 + 2 * t + 8);
    }

    for (int c = 0; c < NCH; c++) {
        const int cur = c & 1;
        // convert current A to limbs: frag regs (g,2t),(g+8,2t),(g,2t+8),(g+8,2t+8)
        uint32_t ah[4], al[4];
        split2(pa[cur][0], ah[0], al[0]);
        split2(pa[cur][2], ah[1], al[1]);
        split2(pa[cur][1], ah[2], al[2]);
        split2(pa[cur][3], ah[3], al[3]);

        // prefetch A for step c+2
        if (c + 2 < NCH) {
            const float* p0 = xr0 + (c + 2) * 16;
            const float* p1 = xr1 + (c + 2) * 16;
            pa[cur][0] = *reinterpret_cast<const float2*>(p0 + 2 * t);
            pa[cur][1] = *reinterpret_cast<const float2*>(p0 + 2 * t + 8);
            pa[cur][2] = *reinterpret_cast<const float2*>(p1 + 2 * t);
            pa[cur][3] = *reinterpret_cast<const float2*>(p1 + 2 * t + 8);
        }

        // load all B fragments for this k-step (L1-resident after first warp)
        uint2 bh[8], bl[8];
        const int bbase = c * 256 + g * 4 + t;
#pragma unroll
        for (int nt = 0; nt < 8; nt++) {
            bh[nt] = g_whp[bbase + nt * 32];
            bl[nt] = g_wlp[bbase + nt * 32];
        }

#pragma unroll
        for (int nt = 0; nt < 8; nt++) {
            mma_fp16(acc0[nt], ah[0], ah[1], ah[2], ah[3], bh[nt].x, bh[nt].y);
            mma_fp16(acc1[nt], ah[0], ah[1], ah[2], ah[3], bl[nt].x, bl[nt].y);
            mma_fp16(acc1[nt], al[0], al[1], al[2], al[3], bh[nt].x, bh[nt].y);
        }
    }

    // ---- epilogue: logits for rows (tok0) and (tok0+8), 16 cols per lane each ----
    float L0[16], L1[16];
    float zacc = 0.0f;
#pragma unroll
    for (int nt = 0; nt < 8; nt++) {
#pragma unroll
        for (int q = 0; q < 2; q++) {
            float v0 = acc0[nt][q]     + acc1[nt][q]     * (1.0f / 2048.0f);
            float v1 = acc0[nt][2 + q] + acc1[nt][2 + q] * (1.0f / 2048.0f);
            L0[nt * 2 + q] = v0;
            L1[nt * 2 + q] = v1;
            zacc += v0 * v0 + v1 * v1;
        }
    }

    // quad-wide max
    float m0 = L0[0], m1 = L1[0];
#pragma unroll
    for (int i = 1; i < 16; i++) { m0 = fmaxf(m0, L0[i]); m1 = fmaxf(m1, L1[i]); }
    m0 = fmaxf(m0, __shfl_xor_sync(0xffffffffu, m0, 1));
    m0 = fmaxf(m0, __shfl_xor_sync(0xffffffffu, m0, 2));
    m1 = fmaxf(m1, __shfl_xor_sync(0xffffffffu, m1, 1));
    m1 = fmaxf(m1, __shfl_xor_sync(0xffffffffu, m1, 2));

    float s0 = 0.0f, s1 = 0.0f;
#pragma unroll
    for (int i = 0; i < 16; i++) {
        L0[i] = expf(L0[i] - m0); s0 += L0[i];
        L1[i] = expf(L1[i] - m1); s1 += L1[i];
    }
    s0 += __shfl_xor_sync(0xffffffffu, s0, 1);
    s0 += __shfl_xor_sync(0xffffffffu, s0, 2);
    s1 += __shfl_xor_sync(0xffffffffu, s1, 1);
    s1 += __shfl_xor_sync(0xffffffffu, s1, 2);
    const float inv0 = 1.0f / s0, inv1 = 1.0f / s1;

    // write routing weights
    float* o0 = out_rw + (size_t)tok0 * NE;
    float* o1 = o0 + (size_t)8 * NE;
#pragma unroll
    for (int nt = 0; nt < 8; nt++) {
        *reinterpret_cast<float2*>(o0 + nt * 8 + 2 * t) =
            make_float2(L0[nt * 2] * inv0, L0[nt * 2 + 1] * inv0);
        *reinterpret_cast<float2*>(o1 + nt * 8 + 2 * t) =
            make_float2(L1[nt * 2] * inv1, L1[nt * 2 + 1] * inv1);
    }

    // per-lane top-2 (cols nt*8+2t, nt*8+2t+1), then quad merge
    float v10 = -1.f, v20 = -1.f, v11 = -1.f, v21 = -1.f;
    int i10 = 0, i20 = 0, i11 = 0, i21 = 0;
#pragma unroll
    for (int nt = 0; nt < 8; nt++) {
#pragma unroll
        for (int q = 0; q < 2; q++) {
            const int col = nt * 8 + 2 * t + q;
            float p0v = L0[nt * 2 + q];
            if (p0v > v10)      { v20 = v10; i20 = i10; v10 = p0v; i10 = col; }
            else if (p0v > v20) { v20 = p0v; i20 = col; }
            float p1v = L1[nt * 2 + q];
            if (p1v > v11)      { v21 = v11; i21 = i11; v11 = p1v; i11 = col; }
            else if (p1v > v21) { v21 = p1v; i21 = col; }
        }
    }
    top2_merge(v10, i10, v20, i20, 1);
    top2_merge(v10, i10, v20, i20, 2);
    top2_merge(v11, i11, v21, i21, 1);
    top2_merge(v11, i11, v21, i21, 2);

    if (t == 0) {
        const float w1 = v10 * inv0, w2 = v20 * inv0;
        const float den = w1 + w2 + 1e-8f;
        g_e12[tok0] = i10 | (i20 << 8);
        g_w12[2 * tok0]     = w1 / den;
        g_w12[2 * tok0 + 1] = w2 / den;
        atomicAdd(&g_cnt1[i10], 1);
    } else if (t == 1) {
        const int tok1 = tok0 + 8;
        const float w1 = v11 * inv1, w2 = v21 * inv1;
        const float den = w1 + w2 + 1e-8f;
        g_e12[tok1] = i11 | (i21 << 8);
        g_w12[2 * tok1]     = w1 / den;
        g_w12[2 * tok1 + 1] = w2 / den;
        atomicAdd(&g_cnt1[i11], 1);
    }

    // z-loss partial
#pragma unroll
    for (int off = 16; off; off >>= 1)
        zacc += __shfl_xor_sync(0xffffffffu, zacc, off);
    if (lane == 0) atomicAdd(&g_zsum, zacc);
}

// ---------------- stage B: dispatch mask + normalized counts ----------------
__global__ __launch_bounds__(256) void dispatch_kernel(float* __restrict__ out_nd)
{
    const int gt = blockIdx.x * 256 + threadIdx.x;
    const int token = gt >> 4;
    const int c4 = gt & 15;
    if (token >= NTOK) return;

    const int e12 = g_e12[token];
    const int e1 = e12 & 0xff, e2 = (e12 >> 8) & 0xff;
    const float w1n = g_w12[2 * token];
    const float w2n = g_w12[2 * token + 1];
    const bool acc2 = (g_cnt1[e2] < CAP);
    const float den = w1n + (acc2 ? w2n : 0.0f) + 1e-8f;
    const float d1 = w1n / den;
    const float d2 = acc2 ? (w2n / den) : 0.0f;

    float4 v = make_float4(0.f, 0.f, 0.f, 0.f);
    const int c0 = c4 * 4;
    int r1 = e1 - c0;
    if (r1 == 0) v.x = d1; else if (r1 == 1) v.y = d1;
    else if (r1 == 2) v.z = d1; else if (r1 == 3) v.w = d1;
    int r2 = e2 - c0;
    if (r2 == 0) v.x = d2; else if (r2 == 1) v.y = d2;
    else if (r2 == 2) v.z = d2; else if (r2 == 3) v.w = d2;

    *reinterpret_cast<float4*>(out_nd + (size_t)token * NE + c0) = v;

    if (c4 == 0) {
        atomicAdd(&g_counts[e1], d1);
        if (acc2) atomicAdd(&g_counts[e2], d2);
    }
}

// ---------------- stage C: scalar loss ----------------
__global__ void loss_kernel(float* __restrict__ out)
{
    const int lane = threadIdx.x;
    const float invN = 1.0f / (float)NTOK;
    const float tgt = 512.0f / (float)NTOK;
    float d0 = g_counts[lane] * invN - tgt;
    float d1 = g_counts[lane + 32] * invN - tgt;
    float s = d0 * d0 + d1 * d1;
#pragma unroll
    for (int off = 16; off; off >>= 1)
        s += __shfl_xor_sync(0xffffffffu, s, off);
    if (lane == 0) {
        float lb = s / 64.0f;
        float z = g_zsum / (float)((size_t)NTOK * NE);
        out[(size_t)2 * NTOK * NE] = 1e-3f * z + 1e-3f * lb;
    }
}

// ---------------- launch ----------------
extern "C" void kernel_launch(void* const* d_in, const int* in_sizes, int n_in,
                              void* d_out, int out_size)
{
    const float* x = (const float*)d_in[0];
    const float* W = (const float*)d_in[1];
    if (n_in >= 2 && in_sizes[0] == NE * DM) {
        x = (const float*)d_in[1];
        W = (const float*)d_in[0];
    }
    float* out = (float*)d_out;

    wconv_kernel<<<128, 256>>>(W);
    init_kernel<<<1, 64>>>();
    gemm_router<<<128, 256>>>(x, out);
    dispatch_kernel<<<(NTOK * 16) / 256, 256>>>(out + (size_t)NTOK * NE);
    loss_kernel<<<1, 32>>>(out);
}